// round 1
// baseline (speedup 1.0000x reference)
#include <cuda_runtime.h>
#include <math.h>

#define NB 8
#define AA 3
#define HH 200
#define WW 336
#define HWP (HH*WW)          // 67200
#define AHW (AA*HWP)         // 201600
#define PRE 2000
#define POST 1000
#define THR 0.7f
#define MAXOFF 4.135166556742356f
#define CAP 4096
#define NBINS 65536
#define MW 32                // ceil(2000/64)
#define MS 2048

__device__ unsigned int        g_hist[NB*NBINS];
__device__ int                 g_cnt[NB];
__device__ unsigned int        g_thr[NB];
__device__ unsigned long long  g_cand[NB*CAP];
__device__ float4              g_boxes[NB*PRE];
__device__ float               g_sc[NB*PRE];
__device__ unsigned long long  g_mask[(size_t)NB*MW*MS];

__device__ __forceinline__ unsigned skey(float x){
    float s = 1.0f/(1.0f + expf(-x));
    return __float_as_uint(s) | 0x80000000u;   // s > 0 always -> orderable key
}

__global__ void k_zero(){
    int i = blockIdx.x*blockDim.x + threadIdx.x;
    if (i < NB*NBINS) g_hist[i] = 0u;
    if (i < NB) g_cnt[i] = 0;
}

__global__ void k_hist(const float* __restrict__ logits){
    int t = blockIdx.x*blockDim.x + threadIdx.x;
    int n = blockIdx.y;
    if (t >= AHW) return;
    unsigned key = skey(logits[(size_t)n*AHW + t]);
    atomicAdd(&g_hist[n*NBINS + (key>>16)], 1u);
}

__global__ void k_thresh(){
    int n = blockIdx.x;
    int tid = threadIdx.x;
    __shared__ unsigned seg[1024];
    __shared__ int tstar;
    const uint4* hp = (const uint4*)(g_hist + n*NBINS + tid*64);
    unsigned s = 0;
    #pragma unroll
    for (int k=0;k<16;k++){ uint4 v = hp[k]; s += v.x+v.y+v.z+v.w; }
    seg[tid]=s; __syncthreads();
    for (int off=1; off<1024; off<<=1){
        unsigned v = (tid+off<1024) ? seg[tid+off] : 0u;
        __syncthreads();
        seg[tid] += v;
        __syncthreads();
    }
    if (seg[tid] >= PRE && (tid==1023 || seg[tid+1] < PRE)) tstar = tid;
    __syncthreads();
    if (tid==0){
        int t = tstar;
        unsigned cum = (t < 1023) ? seg[t+1] : 0u;
        unsigned T = (unsigned)(t*64);
        for (int b = t*64+63; b >= t*64; b--){
            cum += g_hist[n*NBINS + b];
            if (cum >= PRE){ T = (unsigned)b; break; }
        }
        g_thr[n] = (T > 0u) ? (T - 1u) : 0u;   // one-bin safety margin
    }
}

__global__ void k_gather(const float* __restrict__ logits){
    int t = blockIdx.x*blockDim.x + threadIdx.x;
    int n = blockIdx.y;
    if (t >= AHW) return;
    unsigned key = skey(logits[(size_t)n*AHW + t]);
    if ((key>>16) >= g_thr[n]){
        int pos = atomicAdd(&g_cnt[n], 1);
        if (pos < CAP){
            int a = t / HWP;
            int pix = t - a*HWP;
            unsigned idx = (unsigned)(pix*AA + a);   // score-space index
            g_cand[n*CAP + pos] =
                ((unsigned long long)key << 32) | (unsigned long long)(0xFFFFFFFFu - idx);
        }
    }
}

__global__ void k_sortdecode(const float* __restrict__ regs,
                             const float* __restrict__ anchors,
                             const int*   __restrict__ sizes){
    int n = blockIdx.x;
    int tid = threadIdx.x;   // 1024 threads
    __shared__ unsigned long long s[CAP];
    int cnt = g_cnt[n]; if (cnt > CAP) cnt = CAP;
    for (int k = tid; k < CAP; k += 1024)
        s[k] = (k < cnt) ? g_cand[n*CAP + k] : 0ull;
    // bitonic sort, descending (keys unique -> deterministic)
    for (int ksz = 2; ksz <= CAP; ksz <<= 1){
        for (int j = ksz>>1; j > 0; j >>= 1){
            __syncthreads();
            for (int idx = tid; idx < CAP; idx += 1024){
                int p = idx ^ j;
                if (p > idx){
                    unsigned long long a = s[idx], b = s[p];
                    bool desc = ((idx & ksz) == 0);
                    if (desc ? (a < b) : (a > b)){ s[idx] = b; s[p] = a; }
                }
            }
        }
    }
    __syncthreads();
    float fh = (float)sizes[n*2+0];
    float fw = (float)sizes[n*2+1];
    for (int r = tid; r < PRE; r += 1024){
        unsigned long long v = s[r];
        unsigned key = (unsigned)(v >> 32);
        unsigned idx = 0xFFFFFFFFu - (unsigned)(v & 0xFFFFFFFFull);
        float score = __uint_as_float(key ^ 0x80000000u);
        float4 anc = ((const float4*)anchors)[(size_t)n*AHW + idx];
        int a = (int)(idx % (unsigned)AA);
        int pix = (int)(idx / (unsigned)AA);
        const float* rb = regs + (size_t)n*(AA*4*HWP) + (size_t)a*4*HWP + pix;
        float r0 = rb[0];
        float r1 = rb[HWP];
        float r2 = rb[2*HWP];
        float r3 = rb[3*HWP];
        float ws = anc.z - anc.x + 1.0f;
        float hs = anc.w - anc.y + 1.0f;
        float xc = anc.x + 0.5f*ws;
        float yc = anc.y + 0.5f*hs;
        float dw = fminf(r2, MAXOFF);
        float dh = fminf(r3, MAXOFF);
        xc = xc + r0*ws;
        yc = yc + r1*hs;
        ws = ws * expf(dw);
        hs = hs * expf(dh);
        float x1 = xc - 0.5f*ws;
        float y1 = yc - 0.5f*hs;
        float x2 = xc + 0.5f*ws - 1.0f;
        float y2 = yc + 0.5f*hs - 1.0f;
        x1 = fminf(fmaxf(x1, 0.0f), fw - 1.0f);
        y1 = fminf(fmaxf(y1, 0.0f), fh - 1.0f);
        x2 = fminf(fmaxf(x2, 0.0f), fw - 1.0f);
        y2 = fminf(fmaxf(y2, 0.0f), fh - 1.0f);
        g_boxes[n*PRE + r] = make_float4(x1,y1,x2,y2);
        g_sc[n*PRE + r] = score;
    }
}

__global__ void k_mask(){
    int n  = blockIdx.y;
    int bx = blockIdx.x;        // 0..31 (row tile of 64)
    int tid = threadIdx.x;      // 1024
    int w    = tid >> 5;        // word 0..31 (whole warp shares w -> broadcast LDS)
    int lane = tid & 31;
    __shared__ float4 sb[PRE];
    for (int k = tid; k < PRE; k += 1024) sb[k] = g_boxes[n*PRE + k];
    __syncthreads();
    int i0 = bx*64 + lane;
    int i1 = i0 + 32;
    bool v0 = i0 < PRE, v1 = i1 < PRE;
    float4 b0 = v0 ? sb[i0] : make_float4(0,0,0,0);
    float4 b1 = v1 ? sb[i1] : make_float4(0,0,0,0);
    float a0 = (b0.z-b0.x+1.0f)*(b0.w-b0.y+1.0f);
    float a1 = (b1.z-b1.x+1.0f)*(b1.w-b1.y+1.0f);
    unsigned long long bits0=0ull, bits1=0ull;
    int j0 = w*64;
    #pragma unroll 4
    for (int jj=0; jj<64; jj++){
        int j = j0 + jj;
        if (j >= PRE) break;
        float4 bj = sb[j];
        float aj = (bj.z-bj.x+1.0f)*(bj.w-bj.y+1.0f);
        if (v0 && j > i0){
            float xtl=fmaxf(b0.x,bj.x), ytl=fmaxf(b0.y,bj.y);
            float xbr=fminf(b0.z,bj.z), ybr=fminf(b0.w,bj.w);
            float iw=fmaxf(xbr-xtl+1.0f,0.0f), ih=fmaxf(ybr-ytl+1.0f,0.0f);
            float inter=iw*ih;
            if (inter/(a0+aj-inter) > THR) bits0 |= (1ull<<jj);
        }
        if (v1 && j > i1){
            float xtl=fmaxf(b1.x,bj.x), ytl=fmaxf(b1.y,bj.y);
            float xbr=fminf(b1.z,bj.z), ybr=fminf(b1.w,bj.w);
            float iw=fmaxf(xbr-xtl+1.0f,0.0f), ih=fmaxf(ybr-ytl+1.0f,0.0f);
            float inter=iw*ih;
            if (inter/(a1+aj-inter) > THR) bits1 |= (1ull<<jj);
        }
    }
    if (v0) g_mask[((size_t)n*MW + w)*MS + i0] = bits0;
    if (v1) g_mask[((size_t)n*MW + w)*MS + i1] = bits1;
}

__global__ void k_scan(float* __restrict__ out){
    int n = blockIdx.x;
    int tid = threadIdx.x;   // 256
    __shared__ unsigned long long remv[MW];
    __shared__ unsigned long long tmprow[64];
    __shared__ unsigned long long sh_alive;
    __shared__ int kb[MW+1];
    if (tid < MW) remv[tid] = 0ull;
    __syncthreads();
    int w   = tid >> 3;
    int sub = tid & 7;
    for (int blk = 0; blk < MW; blk++){
        int base = blk*64;
        int nrows = PRE - base; if (nrows > 64) nrows = 64;
        if (tid < nrows)
            tmprow[tid] = g_mask[((size_t)n*MW + blk)*MS + base + tid];
        __syncthreads();
        if (tid == 0){
            unsigned long long w0 = remv[blk];
            unsigned long long alive = 0ull;
            for (int r = 0; r < nrows; r++){
                if (!((w0 >> r) & 1ull)){
                    alive |= (1ull << r);
                    w0 |= tmprow[r];
                }
            }
            remv[blk] = w0;
            sh_alive = alive;
        }
        __syncthreads();
        unsigned long long alive = sh_alive;
        unsigned long long acc = 0ull;
        const unsigned long long* mp = &g_mask[((size_t)n*MW + w)*MS + base];
        for (int r = sub; r < nrows; r += 8){
            if ((alive >> r) & 1ull) acc |= mp[r];
        }
        acc |= __shfl_down_sync(0xFFFFFFFFu, acc, 4, 8);
        acc |= __shfl_down_sync(0xFFFFFFFFu, acc, 2, 8);
        acc |= __shfl_down_sync(0xFFFFFFFFu, acc, 1, 8);
        if (sub == 0) remv[w] |= acc;
        __syncthreads();
    }
    if (tid == 0){
        int c = 0;
        for (int ww = 0; ww < MW; ww++){
            kb[ww] = c;
            unsigned long long valid = (ww == MW-1) ? 0xFFFFull : ~0ull;
            c += __popcll((~remv[ww]) & valid);
        }
        kb[MW] = c;
    }
    __syncthreads();
    // stable partition: kept (in order) then suppressed (in order) == post top_k
    for (int i = tid; i < PRE; i += 256){
        int ww = i >> 6, b = i & 63;
        unsigned long long valid = (ww == MW-1) ? 0xFFFFull : ~0ull;
        unsigned long long notr = (~remv[ww]) & valid;
        bool keep = (notr >> b) & 1ull;
        unsigned long long below = b ? (notr & ((~0ull) >> (64 - b))) : 0ull;
        int kbelow = kb[ww] + __popcll(below);
        int pos = keep ? kbelow : (kb[MW] + (i - kbelow));
        if (pos < POST){
            float4 bx = g_boxes[n*PRE + i];
            float sc = keep ? g_sc[n*PRE + i] : -1.0f;
            float* op = out + ((size_t)n*POST + pos)*5;
            op[0]=bx.x; op[1]=bx.y; op[2]=bx.z; op[3]=bx.w; op[4]=sc;
        }
    }
}

extern "C" void kernel_launch(void* const* d_in, const int* in_sizes, int n_in,
                              void* d_out, int out_size){
    (void)in_sizes; (void)n_in; (void)out_size;
    const float* logits  = (const float*)d_in[0];
    const float* regs    = (const float*)d_in[1];
    const float* anchors = (const float*)d_in[2];
    const int*   sizes   = (const int*)d_in[3];
    float* out = (float*)d_out;

    k_zero<<<(NB*NBINS + 255)/256, 256>>>();
    dim3 g((AHW + 255)/256, NB);
    k_hist<<<g, 256>>>(logits);
    k_thresh<<<NB, 1024>>>();
    k_gather<<<g, 256>>>(logits);
    k_sortdecode<<<NB, 1024>>>(regs, anchors, sizes);
    k_mask<<<dim3(32, NB), 1024>>>();
    k_scan<<<NB, 256>>>(out);
}

// round 2
// speedup vs baseline: 1.4854x; 1.4854x over previous
#include <cuda_runtime.h>
#include <math.h>

#define NB 8
#define AA 3
#define HH 200
#define WW 336
#define HWP (HH*WW)          // 67200
#define AHW (AA*HWP)         // 201600
#define AHW4 (AHW/4)         // 50400
#define PRE 2000
#define POST 1000
#define THR 0.7f
#define MAXOFF 4.135166556742356f
#define CAP 4096
#define NBINS 65536
#define MW 32                // ceil(2000/64)
#define ROWS_PAD 2048

__device__ unsigned int        g_hist[NB*NBINS];
__device__ int                 g_cnt[NB];
__device__ unsigned int        g_thr[NB];
__device__ unsigned long long  g_cand[NB*CAP];
__device__ float4              g_boxes[NB*PRE];
__device__ float               g_sc[NB*PRE];
// row-major: g_mask[n][row][word], only words w >= row/64 are valid
__device__ unsigned long long  g_mask[(size_t)NB*ROWS_PAD*MW];

__device__ __forceinline__ unsigned skey(float x){
    float s = 1.0f/(1.0f + expf(-x));
    return __float_as_uint(s) | 0x80000000u;   // s > 0 always -> orderable key
}

__global__ void k_zero(){
    int i = blockIdx.x*blockDim.x + threadIdx.x;
    if (i < NB*NBINS) g_hist[i] = 0u;
    if (i < NB) g_cnt[i] = 0;
}

__global__ void k_hist(const float4* __restrict__ logits){
    int t = blockIdx.x*blockDim.x + threadIdx.x;
    int n = blockIdx.y;
    if (t >= AHW4) return;
    float4 v = logits[(size_t)n*AHW4 + t];
    atomicAdd(&g_hist[n*NBINS + (skey(v.x)>>16)], 1u);
    atomicAdd(&g_hist[n*NBINS + (skey(v.y)>>16)], 1u);
    atomicAdd(&g_hist[n*NBINS + (skey(v.z)>>16)], 1u);
    atomicAdd(&g_hist[n*NBINS + (skey(v.w)>>16)], 1u);
}

__global__ void k_thresh(){
    int n = blockIdx.x;
    int tid = threadIdx.x;
    __shared__ unsigned seg[1024];
    __shared__ int tstar;
    const uint4* hp = (const uint4*)(g_hist + n*NBINS + tid*64);
    unsigned s = 0;
    #pragma unroll
    for (int k=0;k<16;k++){ uint4 v = hp[k]; s += v.x+v.y+v.z+v.w; }
    seg[tid]=s; __syncthreads();
    for (int off=1; off<1024; off<<=1){
        unsigned v = (tid+off<1024) ? seg[tid+off] : 0u;
        __syncthreads();
        seg[tid] += v;
        __syncthreads();
    }
    if (seg[tid] >= PRE && (tid==1023 || seg[tid+1] < PRE)) tstar = tid;
    __syncthreads();
    if (tid==0){
        int t = tstar;
        unsigned cum = (t < 1023) ? seg[t+1] : 0u;
        unsigned T = (unsigned)(t*64);
        for (int b = t*64+63; b >= t*64; b--){
            cum += g_hist[n*NBINS + b];
            if (cum >= PRE){ T = (unsigned)b; break; }
        }
        g_thr[n] = (T > 0u) ? (T - 1u) : 0u;   // one-bin safety margin
    }
}

__global__ void k_gather(const float4* __restrict__ logits){
    int t = blockIdx.x*blockDim.x + threadIdx.x;
    int n = blockIdx.y;
    if (t >= AHW4) return;
    float4 v = logits[(size_t)n*AHW4 + t];
    unsigned thr = g_thr[n];
    float vv[4] = {v.x, v.y, v.z, v.w};
    #pragma unroll
    for (int k=0;k<4;k++){
        unsigned key = skey(vv[k]);
        if ((key>>16) >= thr){
            int pos = atomicAdd(&g_cnt[n], 1);
            if (pos < CAP){
                int el = t*4 + k;
                int a = el / HWP;
                int pix = el - a*HWP;
                unsigned idx = (unsigned)(pix*AA + a);   // score-space index
                g_cand[n*CAP + pos] =
                    ((unsigned long long)key << 32) | (unsigned long long)(0xFFFFFFFFu - idx);
            }
        }
    }
}

__global__ void k_sortdecode(const float* __restrict__ regs,
                             const float* __restrict__ anchors,
                             const int*   __restrict__ sizes){
    int n = blockIdx.x;
    int tid = threadIdx.x;   // 1024 threads
    __shared__ unsigned long long s[CAP];
    int cnt = g_cnt[n]; if (cnt > CAP) cnt = CAP;
    for (int k = tid; k < CAP; k += 1024)
        s[k] = (k < cnt) ? g_cand[n*CAP + k] : 0ull;
    for (int ksz = 2; ksz <= CAP; ksz <<= 1){
        for (int j = ksz>>1; j > 0; j >>= 1){
            __syncthreads();
            for (int idx = tid; idx < CAP; idx += 1024){
                int p = idx ^ j;
                if (p > idx){
                    unsigned long long a = s[idx], b = s[p];
                    bool desc = ((idx & ksz) == 0);
                    if (desc ? (a < b) : (a > b)){ s[idx] = b; s[p] = a; }
                }
            }
        }
    }
    __syncthreads();
    float fh = (float)sizes[n*2+0];
    float fw = (float)sizes[n*2+1];
    for (int r = tid; r < PRE; r += 1024){
        unsigned long long v = s[r];
        unsigned key = (unsigned)(v >> 32);
        unsigned idx = 0xFFFFFFFFu - (unsigned)(v & 0xFFFFFFFFull);
        float score = __uint_as_float(key ^ 0x80000000u);
        float4 anc = ((const float4*)anchors)[(size_t)n*AHW + idx];
        int a = (int)(idx % (unsigned)AA);
        int pix = (int)(idx / (unsigned)AA);
        const float* rb = regs + (size_t)n*(AA*4*HWP) + (size_t)a*4*HWP + pix;
        float r0 = rb[0];
        float r1 = rb[HWP];
        float r2 = rb[2*HWP];
        float r3 = rb[3*HWP];
        float ws = anc.z - anc.x + 1.0f;
        float hs = anc.w - anc.y + 1.0f;
        float xc = anc.x + 0.5f*ws;
        float yc = anc.y + 0.5f*hs;
        float dw = fminf(r2, MAXOFF);
        float dh = fminf(r3, MAXOFF);
        xc = xc + r0*ws;
        yc = yc + r1*hs;
        ws = ws * expf(dw);
        hs = hs * expf(dh);
        float x1 = xc - 0.5f*ws;
        float y1 = yc - 0.5f*hs;
        float x2 = xc + 0.5f*ws - 1.0f;
        float y2 = yc + 0.5f*hs - 1.0f;
        x1 = fminf(fmaxf(x1, 0.0f), fw - 1.0f);
        y1 = fminf(fmaxf(y1, 0.0f), fh - 1.0f);
        x2 = fminf(fmaxf(x2, 0.0f), fw - 1.0f);
        y2 = fminf(fmaxf(y2, 0.0f), fh - 1.0f);
        g_boxes[n*PRE + r] = make_float4(x1,y1,x2,y2);
        g_sc[n*PRE + r] = score;
    }
}

// Upper-triangle tile IoU mask. grid = (528, NB), 256 threads.
__global__ void k_mask(){
    int n = blockIdx.y;
    int p = blockIdx.x;
    int ti = 0;
    while (p >= 32 - ti){ p -= 32 - ti; ti++; }
    int tj = ti + p;

    __shared__ float4 rb[64];
    __shared__ float4 cb[64];
    __shared__ float  ca[64];
    int tid = threadIdx.x;
    if (tid < 64){
        int gi = ti*64 + tid;
        rb[tid] = (gi < PRE) ? g_boxes[n*PRE + gi] : make_float4(0.f,0.f,-1.f,-1.f);
    } else if (tid < 128){
        int t = tid - 64;
        int gj = tj*64 + t;
        float4 b = (gj < PRE) ? g_boxes[n*PRE + gj] : make_float4(0.f,0.f,-1.f,-1.f);
        cb[t] = b;
        ca[t] = (b.z - b.x + 1.0f) * (b.w - b.y + 1.0f);
    }
    __syncthreads();

    int r = tid >> 2;        // 0..63
    int q = tid & 3;
    int i = ti*64 + r;
    float4 b0 = rb[r];
    float a0 = (b0.z - b0.x + 1.0f) * (b0.w - b0.y + 1.0f);

    unsigned long long w = 0ull;
    #pragma unroll 4
    for (int jj = 0; jj < 16; jj++){
        int j = jj*4 + q;            // strided -> conflict-free LDS across q
        int jg = tj*64 + j;
        if (jg < PRE && jg > i){
            float4 bj = cb[j];
            float aj = ca[j];
            float xtl = fmaxf(b0.x, bj.x), ytl = fmaxf(b0.y, bj.y);
            float xbr = fminf(b0.z, bj.z), ybr = fminf(b0.w, bj.w);
            float iw = fmaxf(xbr - xtl + 1.0f, 0.0f);
            float ih = fmaxf(ybr - ytl + 1.0f, 0.0f);
            float inter = iw * ih;
            float denom = a0 + aj - inter;
            if (inter > 0.6f * denom){           // conservative prescreen
                if (inter / denom > THR)         // exact (matches reference)
                    w |= (1ull << j);
            }
        }
    }
    w |= __shfl_xor_sync(0xFFFFFFFFu, w, 1, 4);
    w |= __shfl_xor_sync(0xFFFFFFFFu, w, 2, 4);
    if (q == 0 && i < PRE)
        g_mask[((size_t)n*ROWS_PAD + i)*MW + tj] = w;
}

#define TSTRIDE 33
__global__ void k_scan(float* __restrict__ out){
    int n = blockIdx.x;
    int tid = threadIdx.x;    // 256 = 8 warps
    int lane = tid & 31;
    int wrp  = tid >> 5;
    __shared__ unsigned long long remv[MW];
    __shared__ unsigned long long tile[64*TSTRIDE];
    __shared__ unsigned long long sh_alive;
    __shared__ int kb[MW+1];
    if (tid < MW) remv[tid] = 0ull;
    __syncthreads();

    for (int blk = 0; blk < MW; blk++){
        int base = blk*64;
        int nrows = PRE - base; if (nrows > 64) nrows = 64;
        const unsigned long long* gp = &g_mask[((size_t)n*ROWS_PAD + base)*MW];
        for (int k = tid; k < nrows*MW; k += 256){
            int rr = k >> 5, ww = k & 31;
            tile[rr*TSTRIDE + ww] = gp[k];
        }
        __syncthreads();
        if (tid == 0){
            unsigned long long w0 = remv[blk];
            unsigned long long alive = 0ull;
            #pragma unroll
            for (int rr = 0; rr < 64; rr++){
                if (rr < nrows){
                    unsigned long long m = tile[rr*TSTRIDE + blk];
                    if (!((w0 >> rr) & 1ull)){
                        alive |= (1ull << rr);
                        w0 |= m;
                    }
                }
            }
            remv[blk] = w0;
            sh_alive = alive;
        }
        __syncthreads();
        unsigned long long alive = sh_alive;
        // warp wrp handles rows r = wrp, wrp+8, ...; lane = word index
        unsigned long long acc = 0ull;
        for (int rr = wrp; rr < nrows; rr += 8){
            if ((alive >> rr) & 1ull) acc |= tile[rr*TSTRIDE + lane];
        }
        if (acc && lane > blk) atomicOr(&remv[lane], acc);
        __syncthreads();
    }

    if (tid == 0){
        int c = 0;
        for (int ww = 0; ww < MW; ww++){
            kb[ww] = c;
            unsigned long long valid = (ww == MW-1) ? 0xFFFFull : ~0ull;
            c += __popcll((~remv[ww]) & valid);
        }
        kb[MW] = c;
    }
    __syncthreads();
    for (int i = tid; i < PRE; i += 256){
        int ww = i >> 6, b = i & 63;
        unsigned long long valid = (ww == MW-1) ? 0xFFFFull : ~0ull;
        unsigned long long notr = (~remv[ww]) & valid;
        bool keep = (notr >> b) & 1ull;
        unsigned long long below = b ? (notr & ((~0ull) >> (64 - b))) : 0ull;
        int kbelow = kb[ww] + __popcll(below);
        int pos = keep ? kbelow : (kb[MW] + (i - kbelow));
        if (pos < POST){
            float4 bx = g_boxes[n*PRE + i];
            float sc = keep ? g_sc[n*PRE + i] : -1.0f;
            float* op = out + ((size_t)n*POST + pos)*5;
            op[0]=bx.x; op[1]=bx.y; op[2]=bx.z; op[3]=bx.w; op[4]=sc;
        }
    }
}

extern "C" void kernel_launch(void* const* d_in, const int* in_sizes, int n_in,
                              void* d_out, int out_size){
    (void)in_sizes; (void)n_in; (void)out_size;
    const float* logits  = (const float*)d_in[0];
    const float* regs    = (const float*)d_in[1];
    const float* anchors = (const float*)d_in[2];
    const int*   sizes   = (const int*)d_in[3];
    float* out = (float*)d_out;

    k_zero<<<(NB*NBINS + 255)/256, 256>>>();
    dim3 g((AHW4 + 255)/256, NB);
    k_hist<<<g, 256>>>((const float4*)logits);
    k_thresh<<<NB, 1024>>>();
    k_gather<<<g, 256>>>((const float4*)logits);
    k_sortdecode<<<NB, 1024>>>(regs, anchors, sizes);
    k_mask<<<dim3(528, NB), 256>>>();
    k_scan<<<NB, 256>>>(out);
}